// round 9
// baseline (speedup 1.0000x reference)
#include <cuda_runtime.h>

#define N_NODES 100000
#define E_EDGES 1600000
#define FIN  16
#define FMID 32
#define FOUT 16

#define CHUNK   512
#define NCHUNK  ((N_NODES + CHUNK - 1) / CHUNK)   // 196

// ---------------- device scratch ----------------
__device__ int   g_cnt[N_NODES];          // col histogram (0 at start of each replay)
__device__ int   g_start[N_NODES];        // CSC segment starts
__device__ int   g_end[N_NODES];          // CSC segment ends (start + cnt)
__device__ int   g_row32[E_EDGES];        // int32 rows (converted once)
__device__ int   g_col32[E_EDGES];        // int32 cols
__device__ int   g_rank[E_EDGES];         // arrival rank within col segment
__device__ int   g_srow[E_EDGES];         // rows sorted by col
__device__ int   g_bsum[NCHUNK];          // per-chunk totals
__device__ float g_dinv[N_NODES];
__device__ float g_h1s[N_NODES * FMID];   // (x @ W1) * dinv
__device__ float g_h2s[N_NODES * FOUT];   // (relu(o1) @ W2) * dinv
__device__ int   g_is64;

// ---------------- kernels ----------------

// Fused dtype-detect + col histogram + int32 conversion + rank capture.
// Every block samples the SAME 512 odd words -> identical is64 decision.
__global__ void k_hist(const unsigned int* __restrict__ words,
                       const void* __restrict__ edge_raw, int E) {
    __shared__ unsigned int s_or;
    if (threadIdx.x == 0) s_or = 0u;
    __syncthreads();
    unsigned int acc = words[2 * threadIdx.x + 1] | words[2 * (threadIdx.x + 256) + 1];
    #pragma unroll
    for (int s = 16; s > 0; s >>= 1)
        acc |= __shfl_xor_sync(0xffffffffu, acc, s);
    if ((threadIdx.x & 31) == 0) atomicOr(&s_or, acc);
    __syncthreads();
    const int is64 = (s_or == 0u) ? 1 : 0;
    if (blockIdx.x == 0 && threadIdx.x == 0) g_is64 = is64;

    int e = blockIdx.x * blockDim.x + threadIdx.x;
    if (e >= E) return;
    int r, c;
    if (is64) {
        const long long* p = (const long long*)edge_raw;
        r = (int)p[e];  c = (int)p[E + e];
    } else {
        const int* p = (const int*)edge_raw;
        r = p[e];       c = p[E + e];
    }
    g_row32[e] = r;
    g_col32[e] = c;
    g_rank[e]  = atomicAdd(&g_cnt[c], 1);   // rank is free with the histogram
}

// Per-chunk totals.
__global__ void k_scanA() {
    __shared__ int sh[CHUNK];
    int i = blockIdx.x * CHUNK + threadIdx.x;
    sh[threadIdx.x] = (i < N_NODES) ? g_cnt[i] : 0;
    __syncthreads();
    for (int s = CHUNK / 2; s > 0; s >>= 1) {
        if (threadIdx.x < s) sh[threadIdx.x] += sh[threadIdx.x + s];
        __syncthreads();
    }
    if (threadIdx.x == 0) g_bsum[blockIdx.x] = sh[0];
}

// Fused: chunk-offset reduction + in-chunk scan + dinv + cnt reset
// + lin1 (h1s = (x@W1)*dinv) for this block's 512 nodes.
__global__ void k_scanC_lin1(const float* __restrict__ x,
                             const float* __restrict__ W1) {
    __shared__ int   sh[CHUNK];
    __shared__ float sdinv[CHUNK];
    __shared__ float sW[FIN * FMID];
    __shared__ int   soff[CHUNK];

    soff[threadIdx.x] = (threadIdx.x < blockIdx.x && threadIdx.x < NCHUNK)
                        ? g_bsum[threadIdx.x] : 0;
    for (int t = threadIdx.x; t < FIN * FMID; t += blockDim.x) sW[t] = W1[t];

    int i = blockIdx.x * CHUNK + threadIdx.x;
    int v = (i < N_NODES) ? g_cnt[i] : 0;
    sh[threadIdx.x] = v;
    __syncthreads();
    for (int s = CHUNK / 2; s > 0; s >>= 1) {
        if (threadIdx.x < s) soff[threadIdx.x] += soff[threadIdx.x + s];
        __syncthreads();
    }
    int chunk_off = soff[0];
    for (int s = 1; s < CHUNK; s <<= 1) {
        int add = (threadIdx.x >= s) ? sh[threadIdx.x - s] : 0;
        __syncthreads();
        sh[threadIdx.x] += add;
        __syncthreads();
    }
    float d = rsqrtf((float)(v + 1));
    sdinv[threadIdx.x] = d;
    if (i < N_NODES) {
        int start = chunk_off + sh[threadIdx.x] - v;   // exclusive
        g_start[i] = start;
        g_end[i]   = start + v;
        g_dinv[i]  = d;
        g_cnt[i]   = 0;                                // ready for next replay
    }
    __syncthreads();

    int node_base = blockIdx.x * CHUNK;
    int nloc_count = min(CHUNK, N_NODES - node_base);
    for (int t = threadIdx.x; t < nloc_count * FMID; t += blockDim.x) {
        int nl = t >> 5;
        int f  = t & 31;
        int n  = node_base + nl;
        float acc = 0.0f;
        #pragma unroll
        for (int k = 0; k < FIN; k++)
            acc = fmaf(__ldg(&x[n * FIN + k]), sW[k * FMID + f], acc);
        g_h1s[n * FMID + f] = acc * sdinv[nl];
    }
}

// Atomic-free place: 4 edges per thread via int4 coalesced loads.
__global__ void k_place(int E) {
    int t = blockIdx.x * blockDim.x + threadIdx.x;
    int e4 = t * 4;
    if (e4 + 4 <= E) {
        int4 r  = *(const int4*)&g_row32[e4];
        int4 c  = *(const int4*)&g_col32[e4];
        int4 rk = *(const int4*)&g_rank[e4];
        int p0 = __ldg(&g_start[c.x]) + rk.x;
        int p1 = __ldg(&g_start[c.y]) + rk.y;
        int p2 = __ldg(&g_start[c.z]) + rk.z;
        int p3 = __ldg(&g_start[c.w]) + rk.w;
        g_srow[p0] = r.x;
        g_srow[p1] = r.y;
        g_srow[p2] = r.z;
        g_srow[p3] = r.w;
    } else {
        for (int e = e4; e < E; e++) {
            int c = g_col32[e];
            g_srow[__ldg(&g_start[c]) + g_rank[e]] = g_row32[e];
        }
    }
}

// Fused gather1 + lin2. Warp per node, lane = feature (32).
__global__ void k_gather1_lin2(const float* __restrict__ W2,
                               const float* __restrict__ b1) {
    __shared__ float sW[FMID * FOUT];
    __shared__ float sb[FMID];
    __shared__ float so1[8][FMID];
    for (int t = threadIdx.x; t < FMID * FOUT; t += blockDim.x) sW[t] = W2[t];
    for (int t = threadIdx.x; t < FMID; t += blockDim.x) sb[t] = b1[t];
    __syncthreads();

    int w = (blockIdx.x * blockDim.x + threadIdx.x) >> 5;
    if (w >= N_NODES) return;
    int f  = threadIdx.x & 31;
    int wl = (threadIdx.x >> 5) & 7;

    int j    = g_start[w];
    int epos = g_end[w];
    float acc0 = __ldg(&g_h1s[w * FMID + f]);   // self-loop
    float acc1 = 0.0f;
    for (; j + 8 <= epos; j += 8) {
        int r0 = g_srow[j],   r1 = g_srow[j+1], r2 = g_srow[j+2], r3 = g_srow[j+3];
        int r4 = g_srow[j+4], r5 = g_srow[j+5], r6 = g_srow[j+6], r7 = g_srow[j+7];
        float a0 = __ldg(&g_h1s[r0 * FMID + f]);
        float a1 = __ldg(&g_h1s[r1 * FMID + f]);
        float a2 = __ldg(&g_h1s[r2 * FMID + f]);
        float a3 = __ldg(&g_h1s[r3 * FMID + f]);
        float a4 = __ldg(&g_h1s[r4 * FMID + f]);
        float a5 = __ldg(&g_h1s[r5 * FMID + f]);
        float a6 = __ldg(&g_h1s[r6 * FMID + f]);
        float a7 = __ldg(&g_h1s[r7 * FMID + f]);
        acc0 += (a0 + a1) + (a2 + a3);
        acc1 += (a4 + a5) + (a6 + a7);
    }
    for (; j < epos; j++)
        acc0 += __ldg(&g_h1s[g_srow[j] * FMID + f]);
    float acc = acc0 + acc1;

    float d = g_dinv[w];
    so1[wl][f] = fmaxf(fmaf(acc, d, sb[f]), 0.0f);
    __syncwarp();
    if (f < FOUT) {
        float s = 0.0f;
        #pragma unroll
        for (int k = 0; k < FMID; k++)
            s = fmaf(so1[wl][k], sW[k * FOUT + f], s);
        g_h2s[w * FOUT + f] = s * d;
    }
}

// Fused gather2 + final. Half-warp per node, lane = feature (16).
__global__ void k_gather2_final(const float* __restrict__ fcW,
                                const float* __restrict__ fcb,
                                const float* __restrict__ b2,
                                float* __restrict__ out) {
    int h = (blockIdx.x * blockDim.x + threadIdx.x) >> 4;
    if (h >= N_NODES) return;
    int f = threadIdx.x & 15;

    int j    = g_start[h];
    int epos = g_end[h];
    float acc0 = __ldg(&g_h2s[h * FOUT + f]);   // self-loop
    float acc1 = 0.0f;
    for (; j + 8 <= epos; j += 8) {
        int r0 = g_srow[j],   r1 = g_srow[j+1], r2 = g_srow[j+2], r3 = g_srow[j+3];
        int r4 = g_srow[j+4], r5 = g_srow[j+5], r6 = g_srow[j+6], r7 = g_srow[j+7];
        float a0 = __ldg(&g_h2s[r0 * FOUT + f]);
        float a1 = __ldg(&g_h2s[r1 * FOUT + f]);
        float a2 = __ldg(&g_h2s[r2 * FOUT + f]);
        float a3 = __ldg(&g_h2s[r3 * FOUT + f]);
        float a4 = __ldg(&g_h2s[r4 * FOUT + f]);
        float a5 = __ldg(&g_h2s[r5 * FOUT + f]);
        float a6 = __ldg(&g_h2s[r6 * FOUT + f]);
        float a7 = __ldg(&g_h2s[r7 * FOUT + f]);
        acc0 += (a0 + a1) + (a2 + a3);
        acc1 += (a4 + a5) + (a6 + a7);
    }
    for (; j < epos; j++)
        acc0 += __ldg(&g_h2s[g_srow[j] * FOUT + f]);
    float acc = acc0 + acc1;

    float d = g_dinv[h];
    float v = fmaxf(fmaf(acc, d, __ldg(&b2[f])), 0.0f) * __ldg(&fcW[f]);
    #pragma unroll
    for (int s = 8; s > 0; s >>= 1)
        v += __shfl_xor_sync(0xffffffffu, v, s, 16);
    if (f == 0) out[h] = v + __ldg(&fcb[0]);
}

// ---------------- launch ----------------
extern "C" void kernel_launch(void* const* d_in, const int* in_sizes, int n_in,
                              void* d_out, int out_size) {
    const void*  edge = d_in[0];
    const float* x    = (const float*)d_in[1];
    const float* W1   = (const float*)d_in[2];
    const float* b1   = (const float*)d_in[3];
    const float* W2   = (const float*)d_in[4];
    const float* b2   = (const float*)d_in[5];
    const float* fcW  = (const float*)d_in[6];
    const float* fcb  = (const float*)d_in[7];
    float* out = (float*)d_out;

    const int E = in_sizes[0] / 2;
    const int T = 256;

    k_hist        <<<(E + T - 1) / T, T>>>((const unsigned int*)edge, edge, E);
    k_scanA       <<<NCHUNK, CHUNK>>>();
    k_scanC_lin1  <<<NCHUNK, CHUNK>>>(x, W1);
    k_place       <<<(E / 4 + T - 1) / T, T>>>(E);
    k_gather1_lin2<<<(N_NODES * 32 + T - 1) / T, T>>>(W2, b1);
    k_gather2_final<<<(N_NODES * 16 + T - 1) / T, T>>>(fcW, fcb, b2, out);
}

// round 10
// speedup vs baseline: 1.0942x; 1.0942x over previous
#include <cuda_runtime.h>

#define N_NODES 100000
#define E_EDGES 1600000
#define FIN  16
#define FMID 32
#define FOUT 16
#define CAP  64                            // padded per-node capacity (mean deg 16)

// ---------------- device scratch ----------------
__device__ int   g_cnt[N_NODES];           // arrival counter / degree (0 at replay start)
__device__ int   g_degc[N_NODES];          // min(deg, CAP) snapshot for gathers
__device__ float g_dinv[N_NODES];
__device__ int   g_psrow[N_NODES * CAP];   // padded adjacency (rows by target)
__device__ int   g_spill_r[E_EDGES];       // overflow edges (rank >= CAP)
__device__ int   g_spill_c[E_EDGES];
__device__ int   g_spill_cursor;           // 0 at replay start
__device__ int   g_spill_n;                // snapshot for gathers
__device__ float g_h1s[N_NODES * FMID];    // (x @ W1) * dinv
__device__ float g_h2s[N_NODES * FOUT];    // (relu(o1) @ W2) * dinv

// ---------------- kernels ----------------

// Fused dtype-detect + padded-CSR build. One atomic per edge gives both the
// degree histogram AND the final storage slot (no scan, no place pass).
// Every block samples the SAME 512 odd words -> identical is64 decision.
__global__ void k_build(const unsigned int* __restrict__ words,
                        const void* __restrict__ edge_raw, int E) {
    __shared__ unsigned int s_or;
    if (threadIdx.x == 0) s_or = 0u;
    __syncthreads();
    unsigned int acc = words[2 * threadIdx.x + 1] | words[2 * (threadIdx.x + 256) + 1];
    #pragma unroll
    for (int s = 16; s > 0; s >>= 1)
        acc |= __shfl_xor_sync(0xffffffffu, acc, s);
    if ((threadIdx.x & 31) == 0) atomicOr(&s_or, acc);
    __syncthreads();
    const int is64 = (s_or == 0u) ? 1 : 0;

    int base = (blockIdx.x * blockDim.x + threadIdx.x) * 4;
    if (base >= E) return;
    int n = min(4, E - base);

    int r[4], c[4];
    if (is64) {
        const long long* p = (const long long*)edge_raw;
        #pragma unroll
        for (int k = 0; k < 4; k++) if (k < n) {
            r[k] = (int)p[base + k];
            c[k] = (int)p[E + base + k];
        }
    } else {
        const int* p = (const int*)edge_raw;
        #pragma unroll
        for (int k = 0; k < 4; k++) if (k < n) {
            r[k] = p[base + k];
            c[k] = p[E + base + k];
        }
    }
    int rank[4];
    #pragma unroll
    for (int k = 0; k < 4; k++) if (k < n)
        rank[k] = atomicAdd(&g_cnt[c[k]], 1);
    #pragma unroll
    for (int k = 0; k < 4; k++) if (k < n) {
        if (rank[k] < CAP) {
            g_psrow[c[k] * CAP + rank[k]] = r[k];
        } else {                                   // correctness fallback (empty here)
            int s = atomicAdd(&g_spill_cursor, 1);
            g_spill_c[s] = c[k];
            g_spill_r[s] = r[k];
        }
    }
}

// dinv + h1s = (x@W1)*dinv + counter snapshot/reset. Warp per node (32 lanes).
__global__ void k_lin1(const float* __restrict__ x,
                       const float* __restrict__ W1) {
    __shared__ float sW[FIN * FMID];
    for (int t = threadIdx.x; t < FIN * FMID; t += blockDim.x) sW[t] = W1[t];
    __syncthreads();
    int idx = blockIdx.x * blockDim.x + threadIdx.x;
    if (idx == 0) {                         // snapshot + reset spill cursor
        g_spill_n = g_spill_cursor;
        g_spill_cursor = 0;
    }
    if (idx >= N_NODES * FMID) return;
    int i = idx >> 5;
    int f = idx & 31;
    int deg = g_cnt[i];                     // all lanes read before lane-0 resets
    float d = rsqrtf((float)(deg + 1));     // +1 self-loop
    __syncwarp();
    if (f == 0) {
        g_dinv[i] = d;
        g_degc[i] = min(deg, CAP);
        g_cnt[i]  = 0;                      // ready for next replay
    }
    float acc = 0.0f;
    #pragma unroll
    for (int k = 0; k < FIN; k++)
        acc = fmaf(__ldg(&x[i * FIN + k]), sW[k * FMID + f], acc);
    g_h1s[idx] = acc * d;
}

// Fused gather1 + lin2. Warp per node, lane = feature (32).
__global__ void k_gather1_lin2(const float* __restrict__ W2,
                               const float* __restrict__ b1) {
    __shared__ float sW[FMID * FOUT];
    __shared__ float sb[FMID];
    __shared__ float so1[8][FMID];
    for (int t = threadIdx.x; t < FMID * FOUT; t += blockDim.x) sW[t] = W2[t];
    for (int t = threadIdx.x; t < FMID; t += blockDim.x) sb[t] = b1[t];
    __syncthreads();

    int w = (blockIdx.x * blockDim.x + threadIdx.x) >> 5;
    if (w >= N_NODES) return;
    int f  = threadIdx.x & 31;
    int wl = (threadIdx.x >> 5) & 7;

    const int* adj = &g_psrow[w * CAP];
    int deg = g_degc[w];
    float acc0 = __ldg(&g_h1s[w * FMID + f]);   // self-loop
    float acc1 = 0.0f;
    int j = 0;
    for (; j + 8 <= deg; j += 8) {
        int r0 = adj[j],   r1 = adj[j+1], r2 = adj[j+2], r3 = adj[j+3];
        int r4 = adj[j+4], r5 = adj[j+5], r6 = adj[j+6], r7 = adj[j+7];
        float a0 = __ldg(&g_h1s[r0 * FMID + f]);
        float a1 = __ldg(&g_h1s[r1 * FMID + f]);
        float a2 = __ldg(&g_h1s[r2 * FMID + f]);
        float a3 = __ldg(&g_h1s[r3 * FMID + f]);
        float a4 = __ldg(&g_h1s[r4 * FMID + f]);
        float a5 = __ldg(&g_h1s[r5 * FMID + f]);
        float a6 = __ldg(&g_h1s[r6 * FMID + f]);
        float a7 = __ldg(&g_h1s[r7 * FMID + f]);
        acc0 += (a0 + a1) + (a2 + a3);
        acc1 += (a4 + a5) + (a6 + a7);
    }
    for (; j < deg; j++)
        acc0 += __ldg(&g_h1s[adj[j] * FMID + f]);
    float acc = acc0 + acc1;

    int sn = g_spill_n;                      // 0 for this input; correctness path
    for (int i = 0; i < sn; i++)
        if (g_spill_c[i] == w)
            acc += __ldg(&g_h1s[g_spill_r[i] * FMID + f]);

    float d = g_dinv[w];
    so1[wl][f] = fmaxf(fmaf(acc, d, sb[f]), 0.0f);
    __syncwarp();
    if (f < FOUT) {
        float s = 0.0f;
        #pragma unroll
        for (int k = 0; k < FMID; k++)
            s = fmaf(so1[wl][k], sW[k * FOUT + f], s);
        g_h2s[w * FOUT + f] = s * d;
    }
}

// Fused gather2 + final. Half-warp per node, lane = feature (16).
__global__ void k_gather2_final(const float* __restrict__ fcW,
                                const float* __restrict__ fcb,
                                const float* __restrict__ b2,
                                float* __restrict__ out) {
    int h = (blockIdx.x * blockDim.x + threadIdx.x) >> 4;
    if (h >= N_NODES) return;
    int f = threadIdx.x & 15;

    const int* adj = &g_psrow[h * CAP];
    int deg = g_degc[h];
    float acc0 = __ldg(&g_h2s[h * FOUT + f]);   // self-loop
    float acc1 = 0.0f;
    int j = 0;
    for (; j + 8 <= deg; j += 8) {
        int r0 = adj[j],   r1 = adj[j+1], r2 = adj[j+2], r3 = adj[j+3];
        int r4 = adj[j+4], r5 = adj[j+5], r6 = adj[j+6], r7 = adj[j+7];
        float a0 = __ldg(&g_h2s[r0 * FOUT + f]);
        float a1 = __ldg(&g_h2s[r1 * FOUT + f]);
        float a2 = __ldg(&g_h2s[r2 * FOUT + f]);
        float a3 = __ldg(&g_h2s[r3 * FOUT + f]);
        float a4 = __ldg(&g_h2s[r4 * FOUT + f]);
        float a5 = __ldg(&g_h2s[r5 * FOUT + f]);
        float a6 = __ldg(&g_h2s[r6 * FOUT + f]);
        float a7 = __ldg(&g_h2s[r7 * FOUT + f]);
        acc0 += (a0 + a1) + (a2 + a3);
        acc1 += (a4 + a5) + (a6 + a7);
    }
    for (; j < deg; j++)
        acc0 += __ldg(&g_h2s[adj[j] * FOUT + f]);
    float acc = acc0 + acc1;

    int sn = g_spill_n;
    for (int i = 0; i < sn; i++)
        if (g_spill_c[i] == h)
            acc += __ldg(&g_h2s[g_spill_r[i] * FOUT + f]);

    float d = g_dinv[h];
    float v = fmaxf(fmaf(acc, d, __ldg(&b2[f])), 0.0f) * __ldg(&fcW[f]);
    #pragma unroll
    for (int s = 8; s > 0; s >>= 1)
        v += __shfl_xor_sync(0xffffffffu, v, s, 16);
    if (f == 0) out[h] = v + __ldg(&fcb[0]);
}

// ---------------- launch ----------------
extern "C" void kernel_launch(void* const* d_in, const int* in_sizes, int n_in,
                              void* d_out, int out_size) {
    const void*  edge = d_in[0];
    const float* x    = (const float*)d_in[1];
    const float* W1   = (const float*)d_in[2];
    const float* b1   = (const float*)d_in[3];
    const float* W2   = (const float*)d_in[4];
    const float* b2   = (const float*)d_in[5];
    const float* fcW  = (const float*)d_in[6];
    const float* fcb  = (const float*)d_in[7];
    float* out = (float*)d_out;

    const int E = in_sizes[0] / 2;
    const int T = 256;

    k_build       <<<(E / 4 + T - 1) / T, T>>>((const unsigned int*)edge, edge, E);
    k_lin1        <<<(N_NODES * 32 + T - 1) / T, T>>>(x, W1);
    k_gather1_lin2<<<(N_NODES * 32 + T - 1) / T, T>>>(W2, b1);
    k_gather2_final<<<(N_NODES * 16 + T - 1) / T, T>>>(fcW, fcb, b2, out);
}